// round 8
// baseline (speedup 1.0000x reference)
#include <cuda_runtime.h>

#define N_NODES 50000
#define D 128
#define N_EDGES 800000

// ---------------- scratch (device globals: no allocation allowed) ----------
__device__ __align__(16) float g_h[N_NODES * D];    // layer-1 act (rinv_out-scaled)
__device__ float g_rinv_out[N_NODES];
__device__ float g_rinv_in[N_NODES];
__device__ int   g_deg_out[N_NODES];
__device__ int   g_deg_in[N_NODES];
__device__ int   g_off[N_NODES];                    // CSR bucket start (unordered alloc)
__device__ int   g_cur[N_NODES];                    // fill cursors
__device__ int   g_esrc[N_EDGES];                   // src ids bucketed by dst
__device__ int   g_total;                           // bump allocator

// ---------------- graph preprocessing --------------------------------------

__global__ void zero_deg_kernel() {
    int i = blockIdx.x * blockDim.x + threadIdx.x;
    if (i < N_NODES) { g_deg_out[i] = 0; g_deg_in[i] = 0; }
    if (i == 0) g_total = 0;
}

// NOTE: indices are int32 (JAX x64 disabled => int32 despite jnp.int64 request)
__global__ void deg_kernel(const int* __restrict__ src,
                           const int* __restrict__ dst) {
    int e = blockIdx.x * blockDim.x + threadIdx.x;
    if (e < N_EDGES) {
        atomicAdd(&g_deg_out[src[e]], 1);
        atomicAdd(&g_deg_in[dst[e]], 1);
    }
}

// Bucket allocation (block scan + 1 atomic) fused with rsqrt-degree compute.
__global__ void alloc_rinv_kernel() {
    __shared__ int s[256];
    __shared__ int base;
    int t = threadIdx.x;
    int i = blockIdx.x * 256 + t;
    int d = (i < N_NODES) ? g_deg_in[i] : 0;
    s[t] = d;
    __syncthreads();
    #pragma unroll
    for (int o = 1; o < 256; o <<= 1) {
        int v = (t >= o) ? s[t - o] : 0;
        __syncthreads();
        s[t] += v;
        __syncthreads();
    }
    if (t == 255) base = atomicAdd(&g_total, s[255]);
    __syncthreads();
    if (i < N_NODES) {
        int beg = base + s[t] - d;
        g_off[i] = beg;
        g_cur[i] = beg;
        g_rinv_out[i] = rsqrtf((float)max(g_deg_out[i], 1));
        g_rinv_in[i]  = rsqrtf((float)max(d, 1));
    }
}

__global__ void fill_kernel(const int* __restrict__ src,
                            const int* __restrict__ dst) {
    int e = blockIdx.x * blockDim.x + threadIdx.x;
    if (e < N_EDGES) {
        int pos = atomicAdd(&g_cur[dst[e]], 1);
        g_esrc[pos] = src[e];
    }
}

// ---------------- fused aggregate + tf32 tensor-core GEMM -------------------
// Per block (256 thr, 8 warps): aggregate 64 node rows into a tf32 smem tile
// (no global msg buffer), then compute tile @ W + b with mma.sync.
// Layer 1 (!LAYER2): in = x, edge scale = rinv_out[src]; out = relu(.)*rinv_out -> g_h
// Layer 2 ( LAYER2): in = g_h (pre-scaled);               out = . -> outp
// smem strides padded: SIN_S=132 (mod 32 = 4), SW_S=136 (mod 32 = 8).

#define SIN_S 132
#define SW_S  136

__device__ __forceinline__ float f2tf32(float f) {
    unsigned u;
    asm("cvt.rna.tf32.f32 %0, %1;" : "=r"(u) : "f"(f));
    return __uint_as_float(u);
}

template <bool LAYER2>
__global__ void __launch_bounds__(256)
fused_kernel(const float* __restrict__ xin,
             const float* __restrict__ W,
             const float* __restrict__ b,
             float* __restrict__ outp) {
    __shared__ float sIn[64 * SIN_S];   // aggregated tile, tf32
    __shared__ float sW[16 * SW_S];     // W k-chunk, tf32

    int tid = threadIdx.x;
    int wid = tid >> 5;
    int lane = tid & 31;
    int g = lane >> 2;                  // 0..7
    int t = lane & 3;                   // 0..3
    int rowBase = blockIdx.x * 64;
    const float* in = LAYER2 ? (const float*)g_h : xin;
    float* out = LAYER2 ? outp : (float*)g_h;

    // ---- phase 1: aggregate 8 nodes per warp into sIn ----
    for (int r8 = 0; r8 < 8; r8++) {
        int lr = wid * 8 + r8;
        int v = rowBase + lr;
        float ax = 0.f, ay = 0.f, az = 0.f, aw = 0.f;
        float rs = 0.f;
        if (v < N_NODES) {
            int beg = g_off[v];
            int end = beg + g_deg_in[v];
            rs = g_rinv_in[v];
            int i = beg;
            for (; i + 4 <= end; i += 4) {
                int s0 = g_esrc[i + 0];
                int s1 = g_esrc[i + 1];
                int s2 = g_esrc[i + 2];
                int s3 = g_esrc[i + 3];
                float4 v0 = ((const float4*)(in + (size_t)s0 * D))[lane];
                float4 v1 = ((const float4*)(in + (size_t)s1 * D))[lane];
                float4 v2 = ((const float4*)(in + (size_t)s2 * D))[lane];
                float4 v3 = ((const float4*)(in + (size_t)s3 * D))[lane];
                if (!LAYER2) {
                    float c0 = g_rinv_out[s0], c1 = g_rinv_out[s1];
                    float c2 = g_rinv_out[s2], c3 = g_rinv_out[s3];
                    ax = fmaf(v0.x, c0, fmaf(v1.x, c1, fmaf(v2.x, c2, fmaf(v3.x, c3, ax))));
                    ay = fmaf(v0.y, c0, fmaf(v1.y, c1, fmaf(v2.y, c2, fmaf(v3.y, c3, ay))));
                    az = fmaf(v0.z, c0, fmaf(v1.z, c1, fmaf(v2.z, c2, fmaf(v3.z, c3, az))));
                    aw = fmaf(v0.w, c0, fmaf(v1.w, c1, fmaf(v2.w, c2, fmaf(v3.w, c3, aw))));
                } else {
                    ax += v0.x + v1.x + v2.x + v3.x;
                    ay += v0.y + v1.y + v2.y + v3.y;
                    az += v0.z + v1.z + v2.z + v3.z;
                    aw += v0.w + v1.w + v2.w + v3.w;
                }
            }
            for (; i < end; i++) {
                int s = g_esrc[i];
                float4 vv = ((const float4*)(in + (size_t)s * D))[lane];
                float c = LAYER2 ? 1.f : g_rinv_out[s];
                ax = fmaf(vv.x, c, ax); ay = fmaf(vv.y, c, ay);
                az = fmaf(vv.z, c, az); aw = fmaf(vv.w, c, aw);
            }
        }
        float4 o = make_float4(f2tf32(ax * rs), f2tf32(ay * rs),
                               f2tf32(az * rs), f2tf32(aw * rs));
        *(float4*)&sIn[lr * SIN_S + lane * 4] = o;
    }

    // ---- phase 2: 64x128 tile @ W (128x128), warps tiled 2x4 (32x32 each) ----
    int warp_m = wid >> 2;              // 0..1
    int warp_n = wid & 3;               // 0..3

    float acc[2][4][4];
    #pragma unroll
    for (int mt = 0; mt < 2; mt++)
        #pragma unroll
        for (int nt = 0; nt < 4; nt++)
            #pragma unroll
            for (int r = 0; r < 4; r++) acc[mt][nt][r] = 0.f;

    #pragma unroll
    for (int kc = 0; kc < 8; kc++) {    // 8 chunks of 16 k
        __syncthreads();                // sIn ready (1st iter) / sW reuse safe
        #pragma unroll
        for (int i = 0; i < 2; i++) {
            int idx = tid + 256 * i;
            int wr = idx >> 5;
            int k4 = idx & 31;
            float4 v = ((const float4*)(W + (size_t)(kc * 16 + wr) * D))[k4];
            float4 c = make_float4(f2tf32(v.x), f2tf32(v.y), f2tf32(v.z), f2tf32(v.w));
            *(float4*)&sW[wr * SW_S + k4 * 4] = c;
        }
        __syncthreads();

        #pragma unroll
        for (int ks = 0; ks < 2; ks++) {
            int kb = kc * 16 + ks * 8;      // global k (sIn)
            int kq = ks * 8;                // local k (sW)
            unsigned a[2][4];
            #pragma unroll
            for (int mt = 0; mt < 2; mt++) {
                int r = warp_m * 32 + mt * 16 + g;
                a[mt][0] = __float_as_uint(sIn[r * SIN_S + kb + t]);
                a[mt][1] = __float_as_uint(sIn[(r + 8) * SIN_S + kb + t]);
                a[mt][2] = __float_as_uint(sIn[r * SIN_S + kb + t + 4]);
                a[mt][3] = __float_as_uint(sIn[(r + 8) * SIN_S + kb + t + 4]);
            }
            #pragma unroll
            for (int nt = 0; nt < 4; nt++) {
                int n = warp_n * 32 + nt * 8 + g;
                unsigned b0 = __float_as_uint(sW[(kq + t) * SW_S + n]);
                unsigned b1 = __float_as_uint(sW[(kq + t + 4) * SW_S + n]);
                #pragma unroll
                for (int mt = 0; mt < 2; mt++) {
                    asm volatile(
                        "mma.sync.aligned.m16n8k8.row.col.f32.tf32.tf32.f32 "
                        "{%0,%1,%2,%3}, {%4,%5,%6,%7}, {%8,%9}, {%0,%1,%2,%3};"
                        : "+f"(acc[mt][nt][0]), "+f"(acc[mt][nt][1]),
                          "+f"(acc[mt][nt][2]), "+f"(acc[mt][nt][3])
                        : "r"(a[mt][0]), "r"(a[mt][1]), "r"(a[mt][2]), "r"(a[mt][3]),
                          "r"(b0), "r"(b1));
                }
            }
        }
    }

    // ---- epilogue ----
    #pragma unroll
    for (int mt = 0; mt < 2; mt++) {
        #pragma unroll
        for (int nt = 0; nt < 4; nt++) {
            int col = warp_n * 32 + nt * 8 + t * 2;
            float2 bv = *(const float2*)(b + col);
            int row0 = rowBase + warp_m * 32 + mt * 16 + g;
            int row1 = row0 + 8;
            if (row0 < N_NODES) {
                float v0 = acc[mt][nt][0] + bv.x, v1 = acc[mt][nt][1] + bv.y;
                if (!LAYER2) {
                    float rs = g_rinv_out[row0];
                    v0 = fmaxf(v0, 0.f) * rs; v1 = fmaxf(v1, 0.f) * rs;
                }
                *(float2*)(out + (size_t)row0 * D + col) = make_float2(v0, v1);
            }
            if (row1 < N_NODES) {
                float v2 = acc[mt][nt][2] + bv.x, v3 = acc[mt][nt][3] + bv.y;
                if (!LAYER2) {
                    float rs = g_rinv_out[row1];
                    v2 = fmaxf(v2, 0.f) * rs; v3 = fmaxf(v3, 0.f) * rs;
                }
                *(float2*)(out + (size_t)row1 * D + col) = make_float2(v2, v3);
            }
        }
    }
}

// ---------------- launch ----------------------------------------------------
// Launches ONLY — no runtime API calls, no device-symbol addresses from host.

extern "C" void kernel_launch(void* const* d_in, const int* in_sizes, int n_in,
                              void* d_out, int out_size) {
    const float* x   = (const float*)d_in[0];
    const int*   src = (const int*)d_in[1];
    const int*   dst = (const int*)d_in[2];
    const float* W1  = (const float*)d_in[3];
    const float* b1  = (const float*)d_in[4];
    const float* W2  = (const float*)d_in[5];
    const float* b2  = (const float*)d_in[6];
    float* out = (float*)d_out;

    const int T = 256;
    int nodeBlocks  = (N_NODES + T - 1) / T;
    int edgeBlocks  = (N_EDGES + T - 1) / T;
    int fusedBlocks = (N_NODES + 63) / 64;

    // CSR build (shared by both layers)
    zero_deg_kernel<<<nodeBlocks, T>>>();
    deg_kernel<<<edgeBlocks, T>>>(src, dst);
    alloc_rinv_kernel<<<nodeBlocks, T>>>();
    fill_kernel<<<edgeBlocks, T>>>(src, dst);

    // layer 1: h = relu((Agg x) @ W1 + b1) * rinv_out
    fused_kernel<false><<<fusedBlocks, T>>>(x, W1, b1, nullptr);
    // layer 2: out = (Agg h) @ W2 + b2
    fused_kernel<true><<<fusedBlocks, T>>>(nullptr, W2, b2, out);
}

// round 9
// speedup vs baseline: 1.2765x; 1.2765x over previous
#include <cuda_runtime.h>

#define N_NODES 50000
#define D 128
#define N_EDGES 800000

// ---------------- scratch (device globals: no allocation allowed) ----------
__device__ __align__(16) float g_msg[N_NODES * D];  // aggregated (rinv_in-scaled)
__device__ __align__(16) float g_h[N_NODES * D];    // layer-1 act (rinv_out-scaled)
__device__ float g_rinv_out[N_NODES];
__device__ float g_rinv_in[N_NODES];
__device__ int   g_deg_out[N_NODES];
__device__ int   g_deg_in[N_NODES];
__device__ int   g_off[N_NODES];                    // CSR bucket start (unordered alloc)
__device__ int   g_cur[N_NODES];                    // fill cursors
__device__ int   g_esrc[N_EDGES];                   // src ids bucketed by dst
__device__ int   g_total;                           // bump allocator

// ---------------- graph preprocessing --------------------------------------

__global__ void zero_deg_kernel() {
    int i = blockIdx.x * blockDim.x + threadIdx.x;
    if (i < N_NODES) { g_deg_out[i] = 0; g_deg_in[i] = 0; }
    if (i == 0) g_total = 0;
}

// 4 edges/thread, int4 loads: ILP to hide L2 atomic latency.
// NOTE: indices are int32 (JAX x64 disabled => int32 despite jnp.int64 request)
__global__ void deg_kernel(const int* __restrict__ src,
                           const int* __restrict__ dst) {
    int q = blockIdx.x * blockDim.x + threadIdx.x;   // quad index
    if (q * 4 >= N_EDGES) return;
    int4 s4 = ((const int4*)src)[q];
    int4 d4 = ((const int4*)dst)[q];
    atomicAdd(&g_deg_out[s4.x], 1);
    atomicAdd(&g_deg_out[s4.y], 1);
    atomicAdd(&g_deg_out[s4.z], 1);
    atomicAdd(&g_deg_out[s4.w], 1);
    atomicAdd(&g_deg_in[d4.x], 1);
    atomicAdd(&g_deg_in[d4.y], 1);
    atomicAdd(&g_deg_in[d4.z], 1);
    atomicAdd(&g_deg_in[d4.w], 1);
}

// Bucket allocation (block scan + 1 atomic) fused with rsqrt-degree compute.
__global__ void alloc_rinv_kernel() {
    __shared__ int s[256];
    __shared__ int base;
    int t = threadIdx.x;
    int i = blockIdx.x * 256 + t;
    int d = (i < N_NODES) ? g_deg_in[i] : 0;
    s[t] = d;
    __syncthreads();
    #pragma unroll
    for (int o = 1; o < 256; o <<= 1) {
        int v = (t >= o) ? s[t - o] : 0;
        __syncthreads();
        s[t] += v;
        __syncthreads();
    }
    if (t == 255) base = atomicAdd(&g_total, s[255]);
    __syncthreads();
    if (i < N_NODES) {
        int beg = base + s[t] - d;
        g_off[i] = beg;
        g_cur[i] = beg;
        g_rinv_out[i] = rsqrtf((float)max(g_deg_out[i], 1));
        g_rinv_in[i]  = rsqrtf((float)max(d, 1));
    }
}

// 4 edges/thread, int4 loads: 4 independent atomic->store chains per thread.
__global__ void fill_kernel(const int* __restrict__ src,
                            const int* __restrict__ dst) {
    int q = blockIdx.x * blockDim.x + threadIdx.x;
    if (q * 4 >= N_EDGES) return;
    int4 s4 = ((const int4*)src)[q];
    int4 d4 = ((const int4*)dst)[q];
    int p0 = atomicAdd(&g_cur[d4.x], 1);
    int p1 = atomicAdd(&g_cur[d4.y], 1);
    int p2 = atomicAdd(&g_cur[d4.z], 1);
    int p3 = atomicAdd(&g_cur[d4.w], 1);
    g_esrc[p0] = s4.x;
    g_esrc[p1] = s4.y;
    g_esrc[p2] = s4.z;
    g_esrc[p3] = s4.w;
}

// ---------------- aggregation: one warp per node ----------------------------
// msg[v] = rinv_in[v] * sum_{e: dst=v} scale_e * in[src_e]
template <bool FROM_H>
__global__ void agg_kernel(const float* __restrict__ xin) {
    int gtid = blockIdx.x * blockDim.x + threadIdx.x;
    int v = gtid >> 5;
    int lane = gtid & 31;
    if (v >= N_NODES) return;
    const float* in = FROM_H ? (const float*)g_h : xin;

    int beg = g_off[v];
    int end = beg + g_deg_in[v];
    float ax = 0.f, ay = 0.f, az = 0.f, aw = 0.f;

    int i = beg;
    for (; i + 4 <= end; i += 4) {
        int s0 = g_esrc[i + 0];
        int s1 = g_esrc[i + 1];
        int s2 = g_esrc[i + 2];
        int s3 = g_esrc[i + 3];
        float4 v0 = ((const float4*)(in + (size_t)s0 * D))[lane];
        float4 v1 = ((const float4*)(in + (size_t)s1 * D))[lane];
        float4 v2 = ((const float4*)(in + (size_t)s2 * D))[lane];
        float4 v3 = ((const float4*)(in + (size_t)s3 * D))[lane];
        if (!FROM_H) {
            float c0 = g_rinv_out[s0], c1 = g_rinv_out[s1];
            float c2 = g_rinv_out[s2], c3 = g_rinv_out[s3];
            ax = fmaf(v0.x, c0, fmaf(v1.x, c1, fmaf(v2.x, c2, fmaf(v3.x, c3, ax))));
            ay = fmaf(v0.y, c0, fmaf(v1.y, c1, fmaf(v2.y, c2, fmaf(v3.y, c3, ay))));
            az = fmaf(v0.z, c0, fmaf(v1.z, c1, fmaf(v2.z, c2, fmaf(v3.z, c3, az))));
            aw = fmaf(v0.w, c0, fmaf(v1.w, c1, fmaf(v2.w, c2, fmaf(v3.w, c3, aw))));
        } else {
            ax += v0.x + v1.x + v2.x + v3.x;
            ay += v0.y + v1.y + v2.y + v3.y;
            az += v0.z + v1.z + v2.z + v3.z;
            aw += v0.w + v1.w + v2.w + v3.w;
        }
    }
    for (; i < end; i++) {
        int s = g_esrc[i];
        float4 vv = ((const float4*)(in + (size_t)s * D))[lane];
        float c = FROM_H ? 1.f : g_rinv_out[s];
        ax = fmaf(vv.x, c, ax); ay = fmaf(vv.y, c, ay);
        az = fmaf(vv.z, c, az); aw = fmaf(vv.w, c, aw);
    }

    float rs = g_rinv_in[v];
    ((float4*)(g_msg + (size_t)v * D))[lane] =
        make_float4(ax * rs, ay * rs, az * rs, aw * rs);
}

// ---------------- tensor-core GEMM (tf32 mma.sync) --------------------------
// out[row] = g_msg[row] @ W + b ; TO_H: relu + rinv_out scale into g_h.
// Block 256 threads (8 warps): tile BM=64 x BN=128, K=128 chunked 16.
// Warp tile 16x64 (warp_m = wid>>1, warp_n = wid&1), 8 n-tiles.
#define SIN_S 132
#define SW_S  136

__device__ __forceinline__ float f2tf32(float f) {
    unsigned u;
    asm("cvt.rna.tf32.f32 %0, %1;" : "=r"(u) : "f"(f));
    return __uint_as_float(u);
}

template <bool TO_H>
__global__ void gemm_tc_kernel(const float* __restrict__ W,
                               const float* __restrict__ b,
                               float* __restrict__ outp) {
    __shared__ float sIn[64 * SIN_S];
    __shared__ float sW[16 * SW_S];

    int tid = threadIdx.x;
    int wid = tid >> 5;
    int lane = tid & 31;
    int g = lane >> 2;
    int t = lane & 3;
    int warp_m = wid >> 1;
    int warp_n = wid & 1;
    int rowBase = blockIdx.x * 64;
    float* out = TO_H ? (float*)g_h : outp;

    #pragma unroll
    for (int i = 0; i < 8; i++) {
        int idx = tid + 256 * i;
        int lr = idx >> 5;
        int k4 = idx & 31;
        int row = rowBase + lr;
        float4 v = make_float4(0.f, 0.f, 0.f, 0.f);
        if (row < N_NODES)
            v = ((const float4*)(g_msg + (size_t)row * D))[k4];
        float4 c = make_float4(f2tf32(v.x), f2tf32(v.y), f2tf32(v.z), f2tf32(v.w));
        *(float4*)&sIn[lr * SIN_S + k4 * 4] = c;
    }

    float acc[8][4];
    #pragma unroll
    for (int nt = 0; nt < 8; nt++)
        #pragma unroll
        for (int r = 0; r < 4; r++) acc[nt][r] = 0.f;

    int r0 = warp_m * 16 + g;

    #pragma unroll
    for (int kc = 0; kc < 8; kc++) {
        __syncthreads();
        #pragma unroll
        for (int i = 0; i < 2; i++) {
            int idx = tid + 256 * i;
            int wr = idx >> 5;
            int k4 = idx & 31;
            float4 v = ((const float4*)(W + (size_t)(kc * 16 + wr) * D))[k4];
            float4 c = make_float4(f2tf32(v.x), f2tf32(v.y), f2tf32(v.z), f2tf32(v.w));
            *(float4*)&sW[wr * SW_S + k4 * 4] = c;
        }
        __syncthreads();

        #pragma unroll
        for (int ks = 0; ks < 2; ks++) {
            int kb = kc * 16 + ks * 8;
            int kq = ks * 8;
            unsigned a0 = __float_as_uint(sIn[r0 * SIN_S + kb + t]);
            unsigned a1 = __float_as_uint(sIn[(r0 + 8) * SIN_S + kb + t]);
            unsigned a2 = __float_as_uint(sIn[r0 * SIN_S + kb + t + 4]);
            unsigned a3 = __float_as_uint(sIn[(r0 + 8) * SIN_S + kb + t + 4]);
            #pragma unroll
            for (int nt = 0; nt < 8; nt++) {
                int n = warp_n * 64 + nt * 8 + g;
                unsigned b0 = __float_as_uint(sW[(kq + t) * SW_S + n]);
                unsigned b1 = __float_as_uint(sW[(kq + t + 4) * SW_S + n]);
                asm volatile(
                    "mma.sync.aligned.m16n8k8.row.col.f32.tf32.tf32.f32 "
                    "{%0,%1,%2,%3}, {%4,%5,%6,%7}, {%8,%9}, {%0,%1,%2,%3};"
                    : "+f"(acc[nt][0]), "+f"(acc[nt][1]),
                      "+f"(acc[nt][2]), "+f"(acc[nt][3])
                    : "r"(a0), "r"(a1), "r"(a2), "r"(a3), "r"(b0), "r"(b1));
            }
        }
    }

    #pragma unroll
    for (int nt = 0; nt < 8; nt++) {
        int col = warp_n * 64 + nt * 8 + t * 2;
        float2 bv = *(const float2*)(b + col);
        int row0 = rowBase + warp_m * 16 + g;
        int row1 = row0 + 8;
        if (row0 < N_NODES) {
            float v0 = acc[nt][0] + bv.x, v1 = acc[nt][1] + bv.y;
            if (TO_H) {
                float rs = g_rinv_out[row0];
                v0 = fmaxf(v0, 0.f) * rs; v1 = fmaxf(v1, 0.f) * rs;
            }
            *(float2*)(out + (size_t)row0 * D + col) = make_float2(v0, v1);
        }
        if (row1 < N_NODES) {
            float v2 = acc[nt][2] + bv.x, v3 = acc[nt][3] + bv.y;
            if (TO_H) {
                float rs = g_rinv_out[row1];
                v2 = fmaxf(v2, 0.f) * rs; v3 = fmaxf(v3, 0.f) * rs;
            }
            *(float2*)(out + (size_t)row1 * D + col) = make_float2(v2, v3);
        }
    }
}

// ---------------- launch ----------------------------------------------------
// Launches ONLY — no runtime API calls, no device-symbol addresses from host.

extern "C" void kernel_launch(void* const* d_in, const int* in_sizes, int n_in,
                              void* d_out, int out_size) {
    const float* x   = (const float*)d_in[0];
    const int*   src = (const int*)d_in[1];
    const int*   dst = (const int*)d_in[2];
    const float* W1  = (const float*)d_in[3];
    const float* b1  = (const float*)d_in[4];
    const float* W2  = (const float*)d_in[5];
    const float* b2  = (const float*)d_in[6];
    float* out = (float*)d_out;

    const int T = 256;
    int nodeBlocks  = (N_NODES + T - 1) / T;
    int quadBlocks  = (N_EDGES / 4 + T - 1) / T;
    int aggBlocks   = (int)(((long long)N_NODES * 32 + T - 1) / T);
    int gemmBlocks  = (N_NODES + 63) / 64;

    // CSR build (shared by both layers)
    zero_deg_kernel<<<nodeBlocks, T>>>();
    deg_kernel<<<quadBlocks, T>>>(src, dst);
    alloc_rinv_kernel<<<nodeBlocks, T>>>();
    fill_kernel<<<quadBlocks, T>>>(src, dst);

    // layer 1
    agg_kernel<false><<<aggBlocks, T>>>(x);
    gemm_tc_kernel<true><<<gemmBlocks, T>>>(W1, b1, nullptr);

    // layer 2
    agg_kernel<true><<<aggBlocks, T>>>(nullptr);
    gemm_tc_kernel<false><<<gemmBlocks, T>>>(W2, b2, out);
}

// round 10
// speedup vs baseline: 1.2901x; 1.0107x over previous
#include <cuda_runtime.h>
#include <cuda_fp16.h>

#define N_NODES 50000
#define D 128
#define N_EDGES 800000

// ---------------- scratch (device globals: no allocation allowed) ----------
__device__ __align__(16) float  g_msg[N_NODES * D];  // aggregated (rinv_in-scaled)
__device__ __align__(16) __half g_x16[N_NODES * D];  // fp16 copy of x
__device__ __align__(16) __half g_h16[N_NODES * D];  // layer-1 act (rinv_out-scaled, fp16)
__device__ float g_rinv_out[N_NODES];
__device__ float g_rinv_in[N_NODES];
__device__ int   g_deg_out[N_NODES];
__device__ int   g_deg_in[N_NODES];
__device__ int   g_off[N_NODES];                     // CSR bucket start (unordered alloc)
__device__ int   g_cur[N_NODES];                     // fill cursors
__device__ int   g_esrc[N_EDGES];                    // src ids bucketed by dst
__device__ int   g_total;                            // bump allocator

// ---------------- graph preprocessing --------------------------------------

__global__ void zero_deg_kernel() {
    int i = blockIdx.x * blockDim.x + threadIdx.x;
    if (i < N_NODES) { g_deg_out[i] = 0; g_deg_in[i] = 0; }
    if (i == 0) g_total = 0;
}

// NOTE: indices are int32 (JAX x64 disabled => int32 despite jnp.int64 request)
__global__ void deg_kernel(const int* __restrict__ src,
                           const int* __restrict__ dst) {
    int q = blockIdx.x * blockDim.x + threadIdx.x;   // quad index
    if (q * 4 >= N_EDGES) return;
    int4 s4 = ((const int4*)src)[q];
    int4 d4 = ((const int4*)dst)[q];
    atomicAdd(&g_deg_out[s4.x], 1);
    atomicAdd(&g_deg_out[s4.y], 1);
    atomicAdd(&g_deg_out[s4.z], 1);
    atomicAdd(&g_deg_out[s4.w], 1);
    atomicAdd(&g_deg_in[d4.x], 1);
    atomicAdd(&g_deg_in[d4.y], 1);
    atomicAdd(&g_deg_in[d4.z], 1);
    atomicAdd(&g_deg_in[d4.w], 1);
}

// Bucket allocation (block scan + 1 atomic) fused with rsqrt-degree compute.
__global__ void alloc_rinv_kernel() {
    __shared__ int s[256];
    __shared__ int base;
    int t = threadIdx.x;
    int i = blockIdx.x * 256 + t;
    int d = (i < N_NODES) ? g_deg_in[i] : 0;
    s[t] = d;
    __syncthreads();
    #pragma unroll
    for (int o = 1; o < 256; o <<= 1) {
        int v = (t >= o) ? s[t - o] : 0;
        __syncthreads();
        s[t] += v;
        __syncthreads();
    }
    if (t == 255) base = atomicAdd(&g_total, s[255]);
    __syncthreads();
    if (i < N_NODES) {
        int beg = base + s[t] - d;
        g_off[i] = beg;
        g_cur[i] = beg;
        g_rinv_out[i] = rsqrtf((float)max(g_deg_out[i], 1));
        g_rinv_in[i]  = rsqrtf((float)max(d, 1));
    }
}

__global__ void fill_kernel(const int* __restrict__ src,
                            const int* __restrict__ dst) {
    int q = blockIdx.x * blockDim.x + threadIdx.x;
    if (q * 4 >= N_EDGES) return;
    int4 s4 = ((const int4*)src)[q];
    int4 d4 = ((const int4*)dst)[q];
    int p0 = atomicAdd(&g_cur[d4.x], 1);
    int p1 = atomicAdd(&g_cur[d4.y], 1);
    int p2 = atomicAdd(&g_cur[d4.z], 1);
    int p3 = atomicAdd(&g_cur[d4.w], 1);
    g_esrc[p0] = s4.x;
    g_esrc[p1] = s4.y;
    g_esrc[p2] = s4.z;
    g_esrc[p3] = s4.w;
}

// x fp32 -> fp16 (one pass; halves layer-1 gather traffic)
__global__ void convert_x_kernel(const float* __restrict__ x) {
    int idx = blockIdx.x * blockDim.x + threadIdx.x;   // float4 index
    const int n4 = N_NODES * D / 4;
    if (idx >= n4) return;
    float4 v = ((const float4*)x)[idx];
    __half2 h0 = __floats2half2_rn(v.x, v.y);
    __half2 h1 = __floats2half2_rn(v.z, v.w);
    uint2 pk;
    pk.x = *(unsigned*)&h0;
    pk.y = *(unsigned*)&h1;
    ((uint2*)g_x16)[idx] = pk;
}

// ---------------- aggregation: one warp per node, fp16 gather ---------------
// msg[v] = rinv_in[v] * sum_{e: dst=v} scale_e * in[src_e]
// Layer 1 (!FROM_H): in = g_x16, scale = rinv_out[src]
// Layer 2 ( FROM_H): in = g_h16 (already rinv_out-scaled)
// Each lane covers 4 features (8 bytes) -> 256B coalesced per row.
__device__ __forceinline__ void h2f4(uint2 pk, float& a, float& b, float& c, float& d) {
    float2 lo = __half22float2(*(__half2*)&pk.x);
    float2 hi = __half22float2(*(__half2*)&pk.y);
    a = lo.x; b = lo.y; c = hi.x; d = hi.y;
}

template <bool FROM_H>
__global__ void agg_kernel() {
    int gtid = blockIdx.x * blockDim.x + threadIdx.x;
    int v = gtid >> 5;
    int lane = gtid & 31;
    if (v >= N_NODES) return;
    const __half* in = FROM_H ? (const __half*)g_h16 : (const __half*)g_x16;

    int beg = g_off[v];
    int end = beg + g_deg_in[v];
    float ax = 0.f, ay = 0.f, az = 0.f, aw = 0.f;

    int i = beg;
    for (; i + 4 <= end; i += 4) {
        int s0 = g_esrc[i + 0];
        int s1 = g_esrc[i + 1];
        int s2 = g_esrc[i + 2];
        int s3 = g_esrc[i + 3];
        uint2 p0 = ((const uint2*)(in + (size_t)s0 * D))[lane];
        uint2 p1 = ((const uint2*)(in + (size_t)s1 * D))[lane];
        uint2 p2 = ((const uint2*)(in + (size_t)s2 * D))[lane];
        uint2 p3 = ((const uint2*)(in + (size_t)s3 * D))[lane];
        float x0, y0, z0, w0, x1, y1, z1, w1;
        float x2, y2, z2, w2, x3, y3, z3, w3;
        h2f4(p0, x0, y0, z0, w0);
        h2f4(p1, x1, y1, z1, w1);
        h2f4(p2, x2, y2, z2, w2);
        h2f4(p3, x3, y3, z3, w3);
        if (!FROM_H) {
            float c0 = g_rinv_out[s0], c1 = g_rinv_out[s1];
            float c2 = g_rinv_out[s2], c3 = g_rinv_out[s3];
            ax = fmaf(x0, c0, fmaf(x1, c1, fmaf(x2, c2, fmaf(x3, c3, ax))));
            ay = fmaf(y0, c0, fmaf(y1, c1, fmaf(y2, c2, fmaf(y3, c3, ay))));
            az = fmaf(z0, c0, fmaf(z1, c1, fmaf(z2, c2, fmaf(z3, c3, az))));
            aw = fmaf(w0, c0, fmaf(w1, c1, fmaf(w2, c2, fmaf(w3, c3, aw))));
        } else {
            ax += x0 + x1 + x2 + x3;
            ay += y0 + y1 + y2 + y3;
            az += z0 + z1 + z2 + z3;
            aw += w0 + w1 + w2 + w3;
        }
    }
    for (; i < end; i++) {
        int s = g_esrc[i];
        uint2 p = ((const uint2*)(in + (size_t)s * D))[lane];
        float xx, yy, zz, ww;
        h2f4(p, xx, yy, zz, ww);
        float c = FROM_H ? 1.f : g_rinv_out[s];
        ax = fmaf(xx, c, ax); ay = fmaf(yy, c, ay);
        az = fmaf(zz, c, az); aw = fmaf(ww, c, aw);
    }

    float rs = g_rinv_in[v];
    ((float4*)(g_msg + (size_t)v * D))[lane] =
        make_float4(ax * rs, ay * rs, az * rs, aw * rs);
}

// ---------------- tensor-core GEMM (tf32 mma.sync) --------------------------
// out[row] = g_msg[row] @ W + b
// TO_H: relu + rinv_out scale, write fp16 into g_h16; else fp32 into outp.
#define SIN_S 132
#define SW_S  136

__device__ __forceinline__ float f2tf32(float f) {
    unsigned u;
    asm("cvt.rna.tf32.f32 %0, %1;" : "=r"(u) : "f"(f));
    return __uint_as_float(u);
}

template <bool TO_H>
__global__ void gemm_tc_kernel(const float* __restrict__ W,
                               const float* __restrict__ b,
                               float* __restrict__ outp) {
    __shared__ float sIn[64 * SIN_S];
    __shared__ float sW[16 * SW_S];

    int tid = threadIdx.x;
    int wid = tid >> 5;
    int lane = tid & 31;
    int g = lane >> 2;
    int t = lane & 3;
    int warp_m = wid >> 1;
    int warp_n = wid & 1;
    int rowBase = blockIdx.x * 64;

    #pragma unroll
    for (int i = 0; i < 8; i++) {
        int idx = tid + 256 * i;
        int lr = idx >> 5;
        int k4 = idx & 31;
        int row = rowBase + lr;
        float4 v = make_float4(0.f, 0.f, 0.f, 0.f);
        if (row < N_NODES)
            v = ((const float4*)(g_msg + (size_t)row * D))[k4];
        float4 c = make_float4(f2tf32(v.x), f2tf32(v.y), f2tf32(v.z), f2tf32(v.w));
        *(float4*)&sIn[lr * SIN_S + k4 * 4] = c;
    }

    float acc[8][4];
    #pragma unroll
    for (int nt = 0; nt < 8; nt++)
        #pragma unroll
        for (int r = 0; r < 4; r++) acc[nt][r] = 0.f;

    int r0 = warp_m * 16 + g;

    #pragma unroll
    for (int kc = 0; kc < 8; kc++) {
        __syncthreads();
        #pragma unroll
        for (int i = 0; i < 2; i++) {
            int idx = tid + 256 * i;
            int wr = idx >> 5;
            int k4 = idx & 31;
            float4 v = ((const float4*)(W + (size_t)(kc * 16 + wr) * D))[k4];
            float4 c = make_float4(f2tf32(v.x), f2tf32(v.y), f2tf32(v.z), f2tf32(v.w));
            *(float4*)&sW[wr * SW_S + k4 * 4] = c;
        }
        __syncthreads();

        #pragma unroll
        for (int ks = 0; ks < 2; ks++) {
            int kb = kc * 16 + ks * 8;
            int kq = ks * 8;
            unsigned a0 = __float_as_uint(sIn[r0 * SIN_S + kb + t]);
            unsigned a1 = __float_as_uint(sIn[(r0 + 8) * SIN_S + kb + t]);
            unsigned a2 = __float_as_uint(sIn[r0 * SIN_S + kb + t + 4]);
            unsigned a3 = __float_as_uint(sIn[(r0 + 8) * SIN_S + kb + t + 4]);
            #pragma unroll
            for (int nt = 0; nt < 8; nt++) {
                int n = warp_n * 64 + nt * 8 + g;
                unsigned b0 = __float_as_uint(sW[(kq + t) * SW_S + n]);
                unsigned b1 = __float_as_uint(sW[(kq + t + 4) * SW_S + n]);
                asm volatile(
                    "mma.sync.aligned.m16n8k8.row.col.f32.tf32.tf32.f32 "
                    "{%0,%1,%2,%3}, {%4,%5,%6,%7}, {%8,%9}, {%0,%1,%2,%3};"
                    : "+f"(acc[nt][0]), "+f"(acc[nt][1]),
                      "+f"(acc[nt][2]), "+f"(acc[nt][3])
                    : "r"(a0), "r"(a1), "r"(a2), "r"(a3), "r"(b0), "r"(b1));
            }
        }
    }

    #pragma unroll
    for (int nt = 0; nt < 8; nt++) {
        int col = warp_n * 64 + nt * 8 + t * 2;
        float2 bv = *(const float2*)(b + col);
        int row0 = rowBase + warp_m * 16 + g;
        int row1 = row0 + 8;
        if (row0 < N_NODES) {
            float v0 = acc[nt][0] + bv.x, v1 = acc[nt][1] + bv.y;
            if (TO_H) {
                float rs = g_rinv_out[row0];
                __half2 h = __floats2half2_rn(fmaxf(v0, 0.f) * rs, fmaxf(v1, 0.f) * rs);
                *(__half2*)((__half*)g_h16 + (size_t)row0 * D + col) = h;
            } else {
                *(float2*)(outp + (size_t)row0 * D + col) = make_float2(v0, v1);
            }
        }
        if (row1 < N_NODES) {
            float v2 = acc[nt][2] + bv.x, v3 = acc[nt][3] + bv.y;
            if (TO_H) {
                float rs = g_rinv_out[row1];
                __half2 h = __floats2half2_rn(fmaxf(v2, 0.f) * rs, fmaxf(v3, 0.f) * rs);
                *(__half2*)((__half*)g_h16 + (size_t)row1 * D + col) = h;
            } else {
                *(float2*)(outp + (size_t)row1 * D + col) = make_float2(v2, v3);
            }
        }
    }
}

// ---------------- launch ----------------------------------------------------
// Launches ONLY — no runtime API calls, no device-symbol addresses from host.

extern "C" void kernel_launch(void* const* d_in, const int* in_sizes, int n_in,
                              void* d_out, int out_size) {
    const float* x   = (const float*)d_in[0];
    const int*   src = (const int*)d_in[1];
    const int*   dst = (const int*)d_in[2];
    const float* W1  = (const float*)d_in[3];
    const float* b1  = (const float*)d_in[4];
    const float* W2  = (const float*)d_in[5];
    const float* b2  = (const float*)d_in[6];
    float* out = (float*)d_out;

    const int T = 256;
    int nodeBlocks = (N_NODES + T - 1) / T;
    int quadBlocks = (N_EDGES / 4 + T - 1) / T;
    int vec4Blocks = (N_NODES * D / 4 + T - 1) / T;
    int aggBlocks  = (int)(((long long)N_NODES * 32 + T - 1) / T);
    int gemmBlocks = (N_NODES + 63) / 64;

    // CSR build + x conversion (shared by both layers)
    zero_deg_kernel<<<nodeBlocks, T>>>();
    deg_kernel<<<quadBlocks, T>>>(src, dst);
    alloc_rinv_kernel<<<nodeBlocks, T>>>();
    fill_kernel<<<quadBlocks, T>>>(src, dst);
    convert_x_kernel<<<vec4Blocks, T>>>(x);

    // layer 1
    agg_kernel<false><<<aggBlocks, T>>>();
    gemm_tc_kernel<true><<<gemmBlocks, T>>>(W1, b1, nullptr);

    // layer 2
    agg_kernel<true><<<aggBlocks, T>>>();
    gemm_tc_kernel<false><<<gemmBlocks, T>>>(W2, b2, out);
}

// round 11
// speedup vs baseline: 1.3098x; 1.0153x over previous
#include <cuda_runtime.h>
#include <cuda_fp16.h>

#define N_NODES 50000
#define D 128
#define N_EDGES 800000

// ---------------- scratch (device globals: no allocation allowed) ----------
__device__ __align__(16) float  g_msg[N_NODES * D];  // aggregated (rinv_in-scaled)
__device__ __align__(16) __half g_x16[N_NODES * D];  // fp16 copy of x
__device__ __align__(16) __half g_h16[N_NODES * D];  // layer-1 act (rinv_out-scaled, fp16)
__device__ float g_rinv_out[N_NODES];
__device__ float g_rinv_in[N_NODES];
__device__ int   g_deg_out[N_NODES];
__device__ int   g_deg_in[N_NODES];
__device__ int   g_off[N_NODES];                     // CSR bucket start (unordered alloc)
__device__ int   g_cur[N_NODES];                     // fill cursors
__device__ int   g_esrc[N_EDGES];                    // src ids bucketed by dst
__device__ int   g_total;                            // bump allocator

// ---------------- graph preprocessing --------------------------------------

__global__ void zero_deg_kernel() {
    int i = blockIdx.x * blockDim.x + threadIdx.x;
    if (i < N_NODES) { g_deg_out[i] = 0; g_deg_in[i] = 0; }
    if (i == 0) g_total = 0;
}

// NOTE: indices are int32 (JAX x64 disabled => int32 despite jnp.int64 request)
__global__ void deg_kernel(const int* __restrict__ src,
                           const int* __restrict__ dst) {
    int q = blockIdx.x * blockDim.x + threadIdx.x;   // quad index
    if (q * 4 >= N_EDGES) return;
    int4 s4 = ((const int4*)src)[q];
    int4 d4 = ((const int4*)dst)[q];
    atomicAdd(&g_deg_out[s4.x], 1);
    atomicAdd(&g_deg_out[s4.y], 1);
    atomicAdd(&g_deg_out[s4.z], 1);
    atomicAdd(&g_deg_out[s4.w], 1);
    atomicAdd(&g_deg_in[d4.x], 1);
    atomicAdd(&g_deg_in[d4.y], 1);
    atomicAdd(&g_deg_in[d4.z], 1);
    atomicAdd(&g_deg_in[d4.w], 1);
}

// Bucket allocation (block scan + 1 atomic) fused with rsqrt-degree compute.
__global__ void alloc_rinv_kernel() {
    __shared__ int s[256];
    __shared__ int base;
    int t = threadIdx.x;
    int i = blockIdx.x * 256 + t;
    int d = (i < N_NODES) ? g_deg_in[i] : 0;
    s[t] = d;
    __syncthreads();
    #pragma unroll
    for (int o = 1; o < 256; o <<= 1) {
        int v = (t >= o) ? s[t - o] : 0;
        __syncthreads();
        s[t] += v;
        __syncthreads();
    }
    if (t == 255) base = atomicAdd(&g_total, s[255]);
    __syncthreads();
    if (i < N_NODES) {
        int beg = base + s[t] - d;
        g_off[i] = beg;
        g_cur[i] = beg;
        g_rinv_out[i] = rsqrtf((float)max(g_deg_out[i], 1));
        g_rinv_in[i]  = rsqrtf((float)max(d, 1));
    }
}

__global__ void fill_kernel(const int* __restrict__ src,
                            const int* __restrict__ dst) {
    int q = blockIdx.x * blockDim.x + threadIdx.x;
    if (q * 4 >= N_EDGES) return;
    int4 s4 = ((const int4*)src)[q];
    int4 d4 = ((const int4*)dst)[q];
    int p0 = atomicAdd(&g_cur[d4.x], 1);
    int p1 = atomicAdd(&g_cur[d4.y], 1);
    int p2 = atomicAdd(&g_cur[d4.z], 1);
    int p3 = atomicAdd(&g_cur[d4.w], 1);
    g_esrc[p0] = s4.x;
    g_esrc[p1] = s4.y;
    g_esrc[p2] = s4.z;
    g_esrc[p3] = s4.w;
}

// x fp32 -> fp16 (one pass; halves layer-1 gather traffic)
__global__ void convert_x_kernel(const float* __restrict__ x) {
    int idx = blockIdx.x * blockDim.x + threadIdx.x;   // float4 index
    const int n4 = N_NODES * D / 4;
    if (idx >= n4) return;
    float4 v = ((const float4*)x)[idx];
    __half2 h0 = __floats2half2_rn(v.x, v.y);
    __half2 h1 = __floats2half2_rn(v.z, v.w);
    uint2 pk;
    pk.x = *(unsigned*)&h0;
    pk.y = *(unsigned*)&h1;
    ((uint2*)g_x16)[idx] = pk;
}

// ---------------- aggregation: one warp per node, fp16 gather, MLP=8 --------
// msg[v] = rinv_in[v] * sum_{e: dst=v} scale_e * in[src_e]
__device__ __forceinline__ void h2f4(uint2 pk, float& a, float& b, float& c, float& d) {
    float2 lo = __half22float2(*(__half2*)&pk.x);
    float2 hi = __half22float2(*(__half2*)&pk.y);
    a = lo.x; b = lo.y; c = hi.x; d = hi.y;
}

template <bool FROM_H>
__global__ void agg_kernel() {
    int gtid = blockIdx.x * blockDim.x + threadIdx.x;
    int v = gtid >> 5;
    int lane = gtid & 31;
    if (v >= N_NODES) return;
    const __half* in = FROM_H ? (const __half*)g_h16 : (const __half*)g_x16;

    int beg = g_off[v];
    int end = beg + g_deg_in[v];
    float ax = 0.f, ay = 0.f, az = 0.f, aw = 0.f;

    int i = beg;
    // 8-wide: 8 independent gathers in flight per lane
    for (; i + 8 <= end; i += 8) {
        int s[8];
        #pragma unroll
        for (int j = 0; j < 8; j++) s[j] = g_esrc[i + j];
        uint2 p[8];
        #pragma unroll
        for (int j = 0; j < 8; j++)
            p[j] = ((const uint2*)(in + (size_t)s[j] * D))[lane];
        #pragma unroll
        for (int j = 0; j < 8; j++) {
            float xx, yy, zz, ww;
            h2f4(p[j], xx, yy, zz, ww);
            float c = FROM_H ? 1.f : g_rinv_out[s[j]];
            ax = fmaf(xx, c, ax); ay = fmaf(yy, c, ay);
            az = fmaf(zz, c, az); aw = fmaf(ww, c, aw);
        }
    }
    // 4-wide tail
    for (; i + 4 <= end; i += 4) {
        int s[4];
        #pragma unroll
        for (int j = 0; j < 4; j++) s[j] = g_esrc[i + j];
        uint2 p[4];
        #pragma unroll
        for (int j = 0; j < 4; j++)
            p[j] = ((const uint2*)(in + (size_t)s[j] * D))[lane];
        #pragma unroll
        for (int j = 0; j < 4; j++) {
            float xx, yy, zz, ww;
            h2f4(p[j], xx, yy, zz, ww);
            float c = FROM_H ? 1.f : g_rinv_out[s[j]];
            ax = fmaf(xx, c, ax); ay = fmaf(yy, c, ay);
            az = fmaf(zz, c, az); aw = fmaf(ww, c, aw);
        }
    }
    // scalar tail
    for (; i < end; i++) {
        int s = g_esrc[i];
        uint2 p = ((const uint2*)(in + (size_t)s * D))[lane];
        float xx, yy, zz, ww;
        h2f4(p, xx, yy, zz, ww);
        float c = FROM_H ? 1.f : g_rinv_out[s];
        ax = fmaf(xx, c, ax); ay = fmaf(yy, c, ay);
        az = fmaf(zz, c, az); aw = fmaf(ww, c, aw);
    }

    float rs = g_rinv_in[v];
    ((float4*)(g_msg + (size_t)v * D))[lane] =
        make_float4(ax * rs, ay * rs, az * rs, aw * rs);
}

// ---------------- tensor-core GEMM (tf32 mma.sync) --------------------------
// out[row] = g_msg[row] @ W + b
// TO_H: relu + rinv_out scale, write fp16 into g_h16; else fp32 into outp.
#define SIN_S 132
#define SW_S  136

__device__ __forceinline__ float f2tf32(float f) {
    unsigned u;
    asm("cvt.rna.tf32.f32 %0, %1;" : "=r"(u) : "f"(f));
    return __uint_as_float(u);
}

template <bool TO_H>
__global__ void gemm_tc_kernel(const float* __restrict__ W,
                               const float* __restrict__ b,
                               float* __restrict__ outp) {
    __shared__ float sIn[64 * SIN_S];
    __shared__ float sW[16 * SW_S];

    int tid = threadIdx.x;
    int wid = tid >> 5;
    int lane = tid & 31;
    int g = lane >> 2;
    int t = lane & 3;
    int warp_m = wid >> 1;
    int warp_n = wid & 1;
    int rowBase = blockIdx.x * 64;

    #pragma unroll
    for (int i = 0; i < 8; i++) {
        int idx = tid + 256 * i;
        int lr = idx >> 5;
        int k4 = idx & 31;
        int row = rowBase + lr;
        float4 v = make_float4(0.f, 0.f, 0.f, 0.f);
        if (row < N_NODES)
            v = ((const float4*)(g_msg + (size_t)row * D))[k4];
        float4 c = make_float4(f2tf32(v.x), f2tf32(v.y), f2tf32(v.z), f2tf32(v.w));
        *(float4*)&sIn[lr * SIN_S + k4 * 4] = c;
    }

    float acc[8][4];
    #pragma unroll
    for (int nt = 0; nt < 8; nt++)
        #pragma unroll
        for (int r = 0; r < 4; r++) acc[nt][r] = 0.f;

    int r0 = warp_m * 16 + g;

    #pragma unroll
    for (int kc = 0; kc < 8; kc++) {
        __syncthreads();
        #pragma unroll
        for (int i = 0; i < 2; i++) {
            int idx = tid + 256 * i;
            int wr = idx >> 5;
            int k4 = idx & 31;
            float4 v = ((const float4*)(W + (size_t)(kc * 16 + wr) * D))[k4];
            float4 c = make_float4(f2tf32(v.x), f2tf32(v.y), f2tf32(v.z), f2tf32(v.w));
            *(float4*)&sW[wr * SW_S + k4 * 4] = c;
        }
        __syncthreads();

        #pragma unroll
        for (int ks = 0; ks < 2; ks++) {
            int kb = kc * 16 + ks * 8;
            int kq = ks * 8;
            unsigned a0 = __float_as_uint(sIn[r0 * SIN_S + kb + t]);
            unsigned a1 = __float_as_uint(sIn[(r0 + 8) * SIN_S + kb + t]);
            unsigned a2 = __float_as_uint(sIn[r0 * SIN_S + kb + t + 4]);
            unsigned a3 = __float_as_uint(sIn[(r0 + 8) * SIN_S + kb + t + 4]);
            #pragma unroll
            for (int nt = 0; nt < 8; nt++) {
                int n = warp_n * 64 + nt * 8 + g;
                unsigned b0 = __float_as_uint(sW[(kq + t) * SW_S + n]);
                unsigned b1 = __float_as_uint(sW[(kq + t + 4) * SW_S + n]);
                asm volatile(
                    "mma.sync.aligned.m16n8k8.row.col.f32.tf32.tf32.f32 "
                    "{%0,%1,%2,%3}, {%4,%5,%6,%7}, {%8,%9}, {%0,%1,%2,%3};"
                    : "+f"(acc[nt][0]), "+f"(acc[nt][1]),
                      "+f"(acc[nt][2]), "+f"(acc[nt][3])
                    : "r"(a0), "r"(a1), "r"(a2), "r"(a3), "r"(b0), "r"(b1));
            }
        }
    }

    #pragma unroll
    for (int nt = 0; nt < 8; nt++) {
        int col = warp_n * 64 + nt * 8 + t * 2;
        float2 bv = *(const float2*)(b + col);
        int row0 = rowBase + warp_m * 16 + g;
        int row1 = row0 + 8;
        if (row0 < N_NODES) {
            float v0 = acc[nt][0] + bv.x, v1 = acc[nt][1] + bv.y;
            if (TO_H) {
                float rs = g_rinv_out[row0];
                __half2 h = __floats2half2_rn(fmaxf(v0, 0.f) * rs, fmaxf(v1, 0.f) * rs);
                *(__half2*)((__half*)g_h16 + (size_t)row0 * D + col) = h;
            } else {
                *(float2*)(outp + (size_t)row0 * D + col) = make_float2(v0, v1);
            }
        }
        if (row1 < N_NODES) {
            float v2 = acc[nt][2] + bv.x, v3 = acc[nt][3] + bv.y;
            if (TO_H) {
                float rs = g_rinv_out[row1];
                __half2 h = __floats2half2_rn(fmaxf(v2, 0.f) * rs, fmaxf(v3, 0.f) * rs);
                *(__half2*)((__half*)g_h16 + (size_t)row1 * D + col) = h;
            } else {
                *(float2*)(outp + (size_t)row1 * D + col) = make_float2(v2, v3);
            }
        }
    }
}

// ---------------- launch ----------------------------------------------------
// Launches ONLY — no runtime API calls, no device-symbol addresses from host.

extern "C" void kernel_launch(void* const* d_in, const int* in_sizes, int n_in,
                              void* d_out, int out_size) {
    const float* x   = (const float*)d_in[0];
    const int*   src = (const int*)d_in[1];
    const int*   dst = (const int*)d_in[2];
    const float* W1  = (const float*)d_in[3];
    const float* b1  = (const float*)d_in[4];
    const float* W2  = (const float*)d_in[5];
    const float* b2  = (const float*)d_in[6];
    float* out = (float*)d_out;

    const int T = 256;
    int nodeBlocks = (N_NODES + T - 1) / T;
    int quadBlocks = (N_EDGES / 4 + T - 1) / T;
    int vec4Blocks = (N_NODES * D / 4 + T - 1) / T;
    int aggBlocks  = (int)(((long long)N_NODES * 32 + T - 1) / T);
    int gemmBlocks = (N_NODES + 63) / 64;

    // CSR build + x conversion (shared by both layers)
    zero_deg_kernel<<<nodeBlocks, T>>>();
    deg_kernel<<<quadBlocks, T>>>(src, dst);
    alloc_rinv_kernel<<<nodeBlocks, T>>>();
    fill_kernel<<<quadBlocks, T>>>(src, dst);
    convert_x_kernel<<<vec4Blocks, T>>>(x);

    // layer 1
    agg_kernel<false><<<aggBlocks, T>>>();
    gemm_tc_kernel<true><<<gemmBlocks, T>>>(W1, b1, nullptr);

    // layer 2
    agg_kernel<true><<<aggBlocks, T>>>();
    gemm_tc_kernel<false><<<gemmBlocks, T>>>(W2, b2, out);
}

// round 12
// speedup vs baseline: 1.3193x; 1.0072x over previous
#include <cuda_runtime.h>
#include <cuda_fp16.h>

#define N_NODES 50000
#define D 128
#define N_EDGES 800000

// ---------------- scratch (device globals: no allocation allowed) ----------
__device__ __align__(16) __half g_msg16[N_NODES * D]; // aggregated (rinv_in-scaled)
__device__ __align__(16) __half g_x16[N_NODES * D];   // fp16 copy of x
__device__ __align__(16) __half g_h16[N_NODES * D];   // layer-1 act (rinv_out-scaled)
__device__ float g_rinv_in[N_NODES];
__device__ int   g_deg_out[N_NODES];
__device__ int   g_deg_in[N_NODES];
__device__ int   g_off[N_NODES];                      // CSR bucket start
__device__ int   g_cur[N_NODES];                      // fill cursors
__device__ int   g_esrc[N_EDGES];                     // src ids bucketed by dst
__device__ int   g_total;                             // bump allocator

// ---------------- preprocessing ---------------------------------------------

// x fp32 -> fp16 AND zero the degree counters (first kernel, independent work)
__global__ void convert_x_zero_kernel(const float* __restrict__ x) {
    int idx = blockIdx.x * blockDim.x + threadIdx.x;   // float4 index
    const int n4 = N_NODES * D / 4;
    if (idx < N_NODES) { g_deg_out[idx] = 0; g_deg_in[idx] = 0; }
    if (idx == 0) g_total = 0;
    if (idx >= n4) return;
    float4 v = ((const float4*)x)[idx];
    __half2 h0 = __floats2half2_rn(v.x, v.y);
    __half2 h1 = __floats2half2_rn(v.z, v.w);
    uint2 pk;
    pk.x = *(unsigned*)&h0;
    pk.y = *(unsigned*)&h1;
    ((uint2*)g_x16)[idx] = pk;
}

// in-degrees only (out-degrees are counted in fill_kernel)
// NOTE: indices are int32 (JAX x64 disabled => int32 despite jnp.int64 request)
__global__ void deg_kernel(const int* __restrict__ dst) {
    int q = blockIdx.x * blockDim.x + threadIdx.x;
    if (q * 4 >= N_EDGES) return;
    int4 d4 = ((const int4*)dst)[q];
    atomicAdd(&g_deg_in[d4.x], 1);
    atomicAdd(&g_deg_in[d4.y], 1);
    atomicAdd(&g_deg_in[d4.z], 1);
    atomicAdd(&g_deg_in[d4.w], 1);
}

// Bucket allocation (block scan + 1 atomic) fused with rinv_in compute.
__global__ void alloc_rinv_kernel() {
    __shared__ int s[256];
    __shared__ int base;
    int t = threadIdx.x;
    int i = blockIdx.x * 256 + t;
    int d = (i < N_NODES) ? g_deg_in[i] : 0;
    s[t] = d;
    __syncthreads();
    #pragma unroll
    for (int o = 1; o < 256; o <<= 1) {
        int v = (t >= o) ? s[t - o] : 0;
        __syncthreads();
        s[t] += v;
        __syncthreads();
    }
    if (t == 255) base = atomicAdd(&g_total, s[255]);
    __syncthreads();
    if (i < N_NODES) {
        int beg = base + s[t] - d;
        g_off[i] = beg;
        g_cur[i] = beg;
        g_rinv_in[i] = rsqrtf((float)max(d, 1));
    }
}

// CSR fill + out-degree count (8 independent atomic chains per thread)
__global__ void fill_kernel(const int* __restrict__ src,
                            const int* __restrict__ dst) {
    int q = blockIdx.x * blockDim.x + threadIdx.x;
    if (q * 4 >= N_EDGES) return;
    int4 s4 = ((const int4*)src)[q];
    int4 d4 = ((const int4*)dst)[q];
    atomicAdd(&g_deg_out[s4.x], 1);
    atomicAdd(&g_deg_out[s4.y], 1);
    atomicAdd(&g_deg_out[s4.z], 1);
    atomicAdd(&g_deg_out[s4.w], 1);
    int p0 = atomicAdd(&g_cur[d4.x], 1);
    int p1 = atomicAdd(&g_cur[d4.y], 1);
    int p2 = atomicAdd(&g_cur[d4.z], 1);
    int p3 = atomicAdd(&g_cur[d4.w], 1);
    g_esrc[p0] = s4.x;
    g_esrc[p1] = s4.y;
    g_esrc[p2] = s4.z;
    g_esrc[p3] = s4.w;
}

// ---------------- aggregation: one warp per node, fp16 gather, MLP=8 --------
// msg16[v] = fp16( rinv_in[v] * sum_e scale_e * in[src_e] )
// Layer 1: in = g_x16, scale = rsqrt(deg_out[src]) (deg_out[src] >= 1 by construction)
// Layer 2: in = g_h16 (already rinv_out-scaled), scale = 1
__device__ __forceinline__ void h2f4(uint2 pk, float& a, float& b, float& c, float& d) {
    float2 lo = __half22float2(*(__half2*)&pk.x);
    float2 hi = __half22float2(*(__half2*)&pk.y);
    a = lo.x; b = lo.y; c = hi.x; d = hi.y;
}

template <bool FROM_H>
__global__ void agg_kernel() {
    int gtid = blockIdx.x * blockDim.x + threadIdx.x;
    int v = gtid >> 5;
    int lane = gtid & 31;
    if (v >= N_NODES) return;
    const __half* in = FROM_H ? (const __half*)g_h16 : (const __half*)g_x16;

    int beg = g_off[v];
    int end = beg + g_deg_in[v];
    float ax = 0.f, ay = 0.f, az = 0.f, aw = 0.f;

    int i = beg;
    for (; i + 8 <= end; i += 8) {
        int s[8];
        #pragma unroll
        for (int j = 0; j < 8; j++) s[j] = g_esrc[i + j];
        uint2 p[8];
        #pragma unroll
        for (int j = 0; j < 8; j++)
            p[j] = ((const uint2*)(in + (size_t)s[j] * D))[lane];
        #pragma unroll
        for (int j = 0; j < 8; j++) {
            float xx, yy, zz, ww;
            h2f4(p[j], xx, yy, zz, ww);
            float c = FROM_H ? 1.f : rsqrtf((float)g_deg_out[s[j]]);
            ax = fmaf(xx, c, ax); ay = fmaf(yy, c, ay);
            az = fmaf(zz, c, az); aw = fmaf(ww, c, aw);
        }
    }
    for (; i + 4 <= end; i += 4) {
        int s[4];
        #pragma unroll
        for (int j = 0; j < 4; j++) s[j] = g_esrc[i + j];
        uint2 p[4];
        #pragma unroll
        for (int j = 0; j < 4; j++)
            p[j] = ((const uint2*)(in + (size_t)s[j] * D))[lane];
        #pragma unroll
        for (int j = 0; j < 4; j++) {
            float xx, yy, zz, ww;
            h2f4(p[j], xx, yy, zz, ww);
            float c = FROM_H ? 1.f : rsqrtf((float)g_deg_out[s[j]]);
            ax = fmaf(xx, c, ax); ay = fmaf(yy, c, ay);
            az = fmaf(zz, c, az); aw = fmaf(ww, c, aw);
        }
    }
    for (; i < end; i++) {
        int s = g_esrc[i];
        uint2 p = ((const uint2*)(in + (size_t)s * D))[lane];
        float xx, yy, zz, ww;
        h2f4(p, xx, yy, zz, ww);
        float c = FROM_H ? 1.f : rsqrtf((float)g_deg_out[s]);
        ax = fmaf(xx, c, ax); ay = fmaf(yy, c, ay);
        az = fmaf(zz, c, az); aw = fmaf(ww, c, aw);
    }

    float rs = g_rinv_in[v];
    __half2 h0 = __floats2half2_rn(ax * rs, ay * rs);
    __half2 h1 = __floats2half2_rn(az * rs, aw * rs);
    uint2 pk;
    pk.x = *(unsigned*)&h0;
    pk.y = *(unsigned*)&h1;
    ((uint2*)(g_msg16 + (size_t)v * D))[lane] = pk;
}

// ---------------- tensor-core GEMM (tf32 mma.sync) --------------------------
// out[row] = msg16[row] @ W + b  (fp16 -> tf32 is exact, no double rounding)
// TO_H: relu + rsqrt(deg_out) scale, write fp16 into g_h16; else fp32 into outp.
#define SIN_S 132
#define SW_S  136

__device__ __forceinline__ float f2tf32(float f) {
    unsigned u;
    asm("cvt.rna.tf32.f32 %0, %1;" : "=r"(u) : "f"(f));
    return __uint_as_float(u);
}

template <bool TO_H>
__global__ void gemm_tc_kernel(const float* __restrict__ W,
                               const float* __restrict__ b,
                               float* __restrict__ outp) {
    __shared__ float sIn[64 * SIN_S];
    __shared__ float sW[16 * SW_S];

    int tid = threadIdx.x;
    int wid = tid >> 5;
    int lane = tid & 31;
    int g = lane >> 2;
    int t = lane & 3;
    int warp_m = wid >> 1;
    int warp_n = wid & 1;
    int rowBase = blockIdx.x * 64;

    #pragma unroll
    for (int i = 0; i < 8; i++) {
        int idx = tid + 256 * i;        // 2048 groups of 4 features
        int lr = idx >> 5;
        int k4 = idx & 31;
        int row = rowBase + lr;
        float xx = 0.f, yy = 0.f, zz = 0.f, ww = 0.f;
        if (row < N_NODES) {
            uint2 p = ((const uint2*)(g_msg16 + (size_t)row * D))[k4];
            h2f4(p, xx, yy, zz, ww);    // exact in tf32
        }
        *(float4*)&sIn[lr * SIN_S + k4 * 4] = make_float4(xx, yy, zz, ww);
    }

    float acc[8][4];
    #pragma unroll
    for (int nt = 0; nt < 8; nt++)
        #pragma unroll
        for (int r = 0; r < 4; r++) acc[nt][r] = 0.f;

    int r0 = warp_m * 16 + g;

    #pragma unroll
    for (int kc = 0; kc < 8; kc++) {
        __syncthreads();
        #pragma unroll
        for (int i = 0; i < 2; i++) {
            int idx = tid + 256 * i;
            int wr = idx >> 5;
            int k4 = idx & 31;
            float4 v = ((const float4*)(W + (size_t)(kc * 16 + wr) * D))[k4];
            float4 c = make_float4(f2tf32(v.x), f2tf32(v.y), f2tf32(v.z), f2tf32(v.w));
            *(float4*)&sW[wr * SW_S + k4 * 4] = c;
        }
        __syncthreads();

        #pragma unroll
        for (int ks = 0; ks < 2; ks++) {
            int kb = kc * 16 + ks * 8;
            int kq = ks * 8;
            unsigned a0 = __float_as_uint(sIn[r0 * SIN_S + kb + t]);
            unsigned a1 = __float_as_uint(sIn[(r0 + 8) * SIN_S + kb + t]);
            unsigned a2 = __float_as_uint(sIn[r0 * SIN_S + kb + t + 4]);
            unsigned a3 = __float_as_uint(sIn[(r0 + 8) * SIN_S + kb + t + 4]);
            #pragma unroll
            for (int nt = 0; nt < 8; nt++) {
                int n = warp_n * 64 + nt * 8 + g;
                unsigned b0 = __float_as_uint(sW[(kq + t) * SW_S + n]);
                unsigned b1 = __float_as_uint(sW[(kq + t + 4) * SW_S + n]);
                asm volatile(
                    "mma.sync.aligned.m16n8k8.row.col.f32.tf32.tf32.f32 "
                    "{%0,%1,%2,%3}, {%4,%5,%6,%7}, {%8,%9}, {%0,%1,%2,%3};"
                    : "+f"(acc[nt][0]), "+f"(acc[nt][1]),
                      "+f"(acc[nt][2]), "+f"(acc[nt][3])
                    : "r"(a0), "r"(a1), "r"(a2), "r"(a3), "r"(b0), "r"(b1));
            }
        }
    }

    #pragma unroll
    for (int nt = 0; nt < 8; nt++) {
        int col = warp_n * 64 + nt * 8 + t * 2;
        float2 bv = *(const float2*)(b + col);
        int row0 = rowBase + warp_m * 16 + g;
        int row1 = row0 + 8;
        if (row0 < N_NODES) {
            float v0 = acc[nt][0] + bv.x, v1 = acc[nt][1] + bv.y;
            if (TO_H) {
                float rs = rsqrtf((float)max(g_deg_out[row0], 1));
                __half2 h = __floats2half2_rn(fmaxf(v0, 0.f) * rs, fmaxf(v1, 0.f) * rs);
                *(__half2*)((__half*)g_h16 + (size_t)row0 * D + col) = h;
            } else {
                *(float2*)(outp + (size_t)row0 * D + col) = make_float2(v0, v1);
            }
        }
        if (row1 < N_NODES) {
            float v2 = acc[nt][2] + bv.x, v3 = acc[nt][3] + bv.y;
            if (TO_H) {
                float rs = rsqrtf((float)max(g_deg_out[row1], 1));
                __half2 h = __floats2half2_rn(fmaxf(v2, 0.f) * rs, fmaxf(v3, 0.f) * rs);
                *(__half2*)((__half*)g_h16 + (size_t)row1 * D + col) = h;
            } else {
                *(float2*)(outp + (size_t)row1 * D + col) = make_float2(v2, v3);
            }
        }
    }
}

// ---------------- launch ----------------------------------------------------
// Launches ONLY — no runtime API calls, no device-symbol addresses from host.

extern "C" void kernel_launch(void* const* d_in, const int* in_sizes, int n_in,
                              void* d_out, int out_size) {
    const float* x   = (const float*)d_in[0];
    const int*   src = (const int*)d_in[1];
    const int*   dst = (const int*)d_in[2];
    const float* W1  = (const float*)d_in[3];
    const float* b1  = (const float*)d_in[4];
    const float* W2  = (const float*)d_in[5];
    const float* b2  = (const float*)d_in[6];
    float* out = (float*)d_out;

    const int T = 256;
    int nodeBlocks = (N_NODES + T - 1) / T;
    int quadBlocks = (N_EDGES / 4 + T - 1) / T;
    int vec4Blocks = (N_NODES * D / 4 + T - 1) / T;
    int aggBlocks  = (int)(((long long)N_NODES * 32 + T - 1) / T);
    int gemmBlocks = (N_NODES + 63) / 64;

    // preprocessing: convert x + zero counters, CSR build
    convert_x_zero_kernel<<<vec4Blocks, T>>>(x);
    deg_kernel<<<quadBlocks, T>>>(dst);
    alloc_rinv_kernel<<<nodeBlocks, T>>>();
    fill_kernel<<<quadBlocks, T>>>(src, dst);

    // layer 1
    agg_kernel<false><<<aggBlocks, T>>>();
    gemm_tc_kernel<true><<<gemmBlocks, T>>>(W1, b1, nullptr);

    // layer 2
    agg_kernel<true><<<aggBlocks, T>>>();
    gemm_tc_kernel<false><<<gemmBlocks, T>>>(W2, b2, out);
}

// round 13
// speedup vs baseline: 1.3988x; 1.0603x over previous
#include <cuda_runtime.h>
#include <cuda_fp16.h>

#define N_NODES 50000
#define D 128
#define N_EDGES 800000

// ---------------- scratch (device globals: no allocation allowed) ----------
__device__ __align__(16) __half g_msg16[N_NODES * D]; // aggregated (rinv_in-scaled)
__device__ __align__(16) __half g_x16[N_NODES * D];   // fp16 copy of x
__device__ __align__(16) __half g_h16[N_NODES * D];   // layer-1 act (rinv_out-scaled)
__device__ __align__(16) __half g_w1_16[D * D];       // fp16 W1
__device__ __align__(16) __half g_w2_16[D * D];       // fp16 W2
__device__ float g_rinv_in[N_NODES];
__device__ int   g_deg_out[N_NODES];
__device__ int   g_deg_in[N_NODES];
__device__ int   g_off[N_NODES];                      // CSR bucket start
__device__ int   g_cur[N_NODES];                      // fill cursors
__device__ int   g_esrc[N_EDGES];                     // src ids bucketed by dst
__device__ int   g_total;                             // bump allocator

// ---------------- preprocessing ---------------------------------------------

__device__ __forceinline__ uint2 f4toh4(float4 v) {
    __half2 h0 = __floats2half2_rn(v.x, v.y);
    __half2 h1 = __floats2half2_rn(v.z, v.w);
    uint2 pk;
    pk.x = *(unsigned*)&h0;
    pk.y = *(unsigned*)&h1;
    return pk;
}

// x,W1,W2 fp32 -> fp16 AND zero the degree counters (independent first kernel)
__global__ void convert_zero_kernel(const float* __restrict__ x,
                                    const float* __restrict__ W1,
                                    const float* __restrict__ W2) {
    int idx = blockIdx.x * blockDim.x + threadIdx.x;   // float4 index
    const int n4 = N_NODES * D / 4;
    const int w4 = D * D / 4;                          // 4096
    if (idx < N_NODES) { g_deg_out[idx] = 0; g_deg_in[idx] = 0; }
    if (idx == 0) g_total = 0;
    if (idx < w4) {
        ((uint2*)g_w1_16)[idx] = f4toh4(((const float4*)W1)[idx]);
        ((uint2*)g_w2_16)[idx] = f4toh4(((const float4*)W2)[idx]);
    }
    if (idx >= n4) return;
    ((uint2*)g_x16)[idx] = f4toh4(((const float4*)x)[idx]);
}

// in-degrees only (out-degrees are counted in fill_kernel)
// NOTE: indices are int32 (JAX x64 disabled => int32 despite jnp.int64 request)
__global__ void deg_kernel(const int* __restrict__ dst) {
    int q = blockIdx.x * blockDim.x + threadIdx.x;
    if (q * 4 >= N_EDGES) return;
    int4 d4 = ((const int4*)dst)[q];
    atomicAdd(&g_deg_in[d4.x], 1);
    atomicAdd(&g_deg_in[d4.y], 1);
    atomicAdd(&g_deg_in[d4.z], 1);
    atomicAdd(&g_deg_in[d4.w], 1);
}

// Bucket allocation (block scan + 1 atomic) fused with rinv_in compute.
__global__ void alloc_rinv_kernel() {
    __shared__ int s[256];
    __shared__ int base;
    int t = threadIdx.x;
    int i = blockIdx.x * 256 + t;
    int d = (i < N_NODES) ? g_deg_in[i] : 0;
    s[t] = d;
    __syncthreads();
    #pragma unroll
    for (int o = 1; o < 256; o <<= 1) {
        int v = (t >= o) ? s[t - o] : 0;
        __syncthreads();
        s[t] += v;
        __syncthreads();
    }
    if (t == 255) base = atomicAdd(&g_total, s[255]);
    __syncthreads();
    if (i < N_NODES) {
        int beg = base + s[t] - d;
        g_off[i] = beg;
        g_cur[i] = beg;
        g_rinv_in[i] = rsqrtf((float)max(d, 1));
    }
}

// CSR fill + out-degree count (8 independent atomic chains per thread)
__global__ void fill_kernel(const int* __restrict__ src,
                            const int* __restrict__ dst) {
    int q = blockIdx.x * blockDim.x + threadIdx.x;
    if (q * 4 >= N_EDGES) return;
    int4 s4 = ((const int4*)src)[q];
    int4 d4 = ((const int4*)dst)[q];
    atomicAdd(&g_deg_out[s4.x], 1);
    atomicAdd(&g_deg_out[s4.y], 1);
    atomicAdd(&g_deg_out[s4.z], 1);
    atomicAdd(&g_deg_out[s4.w], 1);
    int p0 = atomicAdd(&g_cur[d4.x], 1);
    int p1 = atomicAdd(&g_cur[d4.y], 1);
    int p2 = atomicAdd(&g_cur[d4.z], 1);
    int p3 = atomicAdd(&g_cur[d4.w], 1);
    g_esrc[p0] = s4.x;
    g_esrc[p1] = s4.y;
    g_esrc[p2] = s4.z;
    g_esrc[p3] = s4.w;
}

// ---------------- aggregation: one warp per node, fp16 gather, MLP=8 --------
__device__ __forceinline__ void h2f4(uint2 pk, float& a, float& b, float& c, float& d) {
    float2 lo = __half22float2(*(__half2*)&pk.x);
    float2 hi = __half22float2(*(__half2*)&pk.y);
    a = lo.x; b = lo.y; c = hi.x; d = hi.y;
}

template <bool FROM_H>
__global__ void agg_kernel() {
    int gtid = blockIdx.x * blockDim.x + threadIdx.x;
    int v = gtid >> 5;
    int lane = gtid & 31;
    if (v >= N_NODES) return;
    const __half* in = FROM_H ? (const __half*)g_h16 : (const __half*)g_x16;

    int beg = g_off[v];
    int end = beg + g_deg_in[v];
    float ax = 0.f, ay = 0.f, az = 0.f, aw = 0.f;

    int i = beg;
    for (; i + 8 <= end; i += 8) {
        int s[8];
        #pragma unroll
        for (int j = 0; j < 8; j++) s[j] = g_esrc[i + j];
        uint2 p[8];
        #pragma unroll
        for (int j = 0; j < 8; j++)
            p[j] = ((const uint2*)(in + (size_t)s[j] * D))[lane];
        #pragma unroll
        for (int j = 0; j < 8; j++) {
            float xx, yy, zz, ww;
            h2f4(p[j], xx, yy, zz, ww);
            float c = FROM_H ? 1.f : rsqrtf((float)g_deg_out[s[j]]);
            ax = fmaf(xx, c, ax); ay = fmaf(yy, c, ay);
            az = fmaf(zz, c, az); aw = fmaf(ww, c, aw);
        }
    }
    for (; i + 4 <= end; i += 4) {
        int s[4];
        #pragma unroll
        for (int j = 0; j < 4; j++) s[j] = g_esrc[i + j];
        uint2 p[4];
        #pragma unroll
        for (int j = 0; j < 4; j++)
            p[j] = ((const uint2*)(in + (size_t)s[j] * D))[lane];
        #pragma unroll
        for (int j = 0; j < 4; j++) {
            float xx, yy, zz, ww;
            h2f4(p[j], xx, yy, zz, ww);
            float c = FROM_H ? 1.f : rsqrtf((float)g_deg_out[s[j]]);
            ax = fmaf(xx, c, ax); ay = fmaf(yy, c, ay);
            az = fmaf(zz, c, az); aw = fmaf(ww, c, aw);
        }
    }
    for (; i < end; i++) {
        int s = g_esrc[i];
        uint2 p = ((const uint2*)(in + (size_t)s * D))[lane];
        float xx, yy, zz, ww;
        h2f4(p, xx, yy, zz, ww);
        float c = FROM_H ? 1.f : rsqrtf((float)g_deg_out[s]);
        ax = fmaf(xx, c, ax); ay = fmaf(yy, c, ay);
        az = fmaf(zz, c, az); aw = fmaf(ww, c, aw);
    }

    float rs = g_rinv_in[v];
    __half2 h0 = __floats2half2_rn(ax * rs, ay * rs);
    __half2 h1 = __floats2half2_rn(az * rs, aw * rs);
    uint2 pk;
    pk.x = *(unsigned*)&h0;
    pk.y = *(unsigned*)&h1;
    ((uint2*)(g_msg16 + (size_t)v * D))[lane] = pk;
}

// ---------------- fp16 HMMA GEMM (m16n8k16 + ldmatrix) ----------------------
// out[row] = msg16[row] @ W16 + b ; BM=128, BN=128, 8 warps (16 rows each).
// TO_H: relu + rsqrt(deg_out) scale -> g_h16 fp16; else fp32 -> outp.
// LDA/LDB = 136 halfs (272 B): 68 words % 32 = 4 -> conflict-free ldmatrix.
#define LDA 136
#define LDB 136

template <bool TO_H>
__global__ void __launch_bounds__(256)
gemm_hmma_kernel(const float* __restrict__ b, float* __restrict__ outp) {
    __shared__ __half sA[128 * LDA];   // 34816 B
    __shared__ __half sB[32 * LDB];    //  8704 B

    int tid = threadIdx.x;
    int wid = tid >> 5;
    int lane = tid & 31;
    int g = lane >> 2;                 // 0..7
    int t = lane & 3;                  // 0..3
    int tquad = lane >> 3;             // 0..3  (ldmatrix tile id)
    int trow = lane & 7;               // 0..7  (row within tile)
    int rowBase = blockIdx.x * 128;
    const __half* W16 = TO_H ? (const __half*)g_w1_16 : (const __half*)g_w2_16;

    // fill sA: 128 rows x 128 halfs (uint4 = 8 halfs), 2048 uint4, 8/thread
    #pragma unroll
    for (int i = 0; i < 8; i++) {
        int idx = tid + 256 * i;
        int lr = idx >> 4;             // local row
        int c = idx & 15;              // uint4 col
        int row = rowBase + lr;
        uint4 v = make_uint4(0u, 0u, 0u, 0u);
        if (row < N_NODES)
            v = ((const uint4*)(g_msg16 + (size_t)row * D))[c];
        *(uint4*)&sA[lr * LDA + c * 8] = v;
    }

    float acc[16][4];
    #pragma unroll
    for (int nt = 0; nt < 16; nt++)
        #pragma unroll
        for (int r = 0; r < 4; r++) acc[nt][r] = 0.f;

    // A fragment lane row (fixed per lane): m = wid*16 + (tquad&1)*8 + trow
    int am = wid * 16 + (tquad & 1) * 8 + trow;

    #pragma unroll
    for (int kc = 0; kc < 4; kc++) {   // 4 chunks of 32 k
        __syncthreads();
        // fill sB: 32 rows x 128 halfs = 512 uint4, 2/thread
        #pragma unroll
        for (int i = 0; i < 2; i++) {
            int idx = tid + 256 * i;
            int wr = idx >> 4;
            int c = idx & 15;
            *(uint4*)&sB[wr * LDB + c * 8] =
                ((const uint4*)(W16 + (size_t)(kc * 32 + wr) * D))[c];
        }
        __syncthreads();

        #pragma unroll
        for (int ks = 0; ks < 2; ks++) {   // two k16 steps per chunk
            int kb = kc * 32 + ks * 16;    // global k base (sA cols)
            unsigned a0, a1, a2, a3;
            {
                unsigned aaddr = (unsigned)__cvta_generic_to_shared(
                    &sA[am * LDA + kb + (tquad >> 1) * 8]);
                asm volatile(
                    "ldmatrix.sync.aligned.m8n8.x4.shared.b16 {%0,%1,%2,%3}, [%4];"
                    : "=r"(a0), "=r"(a1), "=r"(a2), "=r"(a3) : "r"(aaddr));
            }
            // B: local chunk rows = ks*16 + (tquad&1)*8 + trow
            int brow = ks * 16 + (tquad & 1) * 8 + trow;
            #pragma unroll
            for (int nt2 = 0; nt2 < 8; nt2++) {    // 2 n-tiles per ldmatrix
                int n0 = nt2 * 16;
                unsigned b0, b1, b2, b3;
                unsigned baddr = (unsigned)__cvta_generic_to_shared(
                    &sB[brow * LDB + n0 + (tquad >> 1) * 8]);
                asm volatile(
                    "ldmatrix.sync.aligned.m8n8.x4.trans.shared.b16 {%0,%1,%2,%3}, [%4];"
                    : "=r"(b0), "=r"(b1), "=r"(b2), "=r"(b3) : "r"(baddr));
                asm volatile(
                    "mma.sync.aligned.m16n8k16.row.col.f32.f16.f16.f32 "
                    "{%0,%1,%2,%3}, {%4,%5,%6,%7}, {%8,%9}, {%0,%1,%2,%3};"
                    : "+f"(acc[nt2 * 2][0]), "+f"(acc[nt2 * 2][1]),
                      "+f"(acc[nt2 * 2][2]), "+f"(acc[nt2 * 2][3])
                    : "r"(a0), "r"(a1), "r"(a2), "r"(a3), "r"(b0), "r"(b1));
                asm volatile(
                    "mma.sync.aligned.m16n8k16.row.col.f32.f16.f16.f32 "
                    "{%0,%1,%2,%3}, {%4,%5,%6,%7}, {%8,%9}, {%0,%1,%2,%3};"
                    : "+f"(acc[nt2 * 2 + 1][0]), "+f"(acc[nt2 * 2 + 1][1]),
                      "+f"(acc[nt2 * 2 + 1][2]), "+f"(acc[nt2 * 2 + 1][3])
                    : "r"(a0), "r"(a1), "r"(a2), "r"(a3), "r"(b2), "r"(b3));
            }
        }
    }

    // epilogue: c-fragment rows g / g+8, cols nt*8 + t*2 (+1)
    #pragma unroll
    for (int nt = 0; nt < 16; nt++) {
        int col = nt * 8 + t * 2;
        float2 bv = *(const float2*)(b + col);
        int row0 = rowBase + wid * 16 + g;
        int row1 = row0 + 8;
        if (row0 < N_NODES) {
            float v0 = acc[nt][0] + bv.x, v1 = acc[nt][1] + bv.y;
            if (TO_H) {
                float rs = rsqrtf((float)max(g_deg_out[row0], 1));
                __half2 h = __floats2half2_rn(fmaxf(v0, 0.f) * rs, fmaxf(v1, 0.f) * rs);
                *(__half2*)((__half*)g_h16 + (size_t)row0 * D + col) = h;
            } else {
                *(float2*)(outp + (size_t)row0 * D + col) = make_float2(v0, v1);
            }
        }
        if (row1 < N_NODES) {
            float v2 = acc[nt][2] + bv.x, v3 = acc[nt][3] + bv.y;
            if (TO_H) {
                float rs = rsqrtf((float)max(g_deg_out[row1], 1));
                __half2 h = __floats2half2_rn(fmaxf(v2, 0.f) * rs, fmaxf(v3, 0.f) * rs);
                *(__half2*)((__half*)g_h16 + (size_t)row1 * D + col) = h;
            } else {
                *(float2*)(outp + (size_t)row1 * D + col) = make_float2(v2, v3);
            }
        }
    }
}

// ---------------- launch ----------------------------------------------------
// Launches ONLY — no runtime API calls, no device-symbol addresses from host.

extern "C" void kernel_launch(void* const* d_in, const int* in_sizes, int n_in,
                              void* d_out, int out_size) {
    const float* x   = (const float*)d_in[0];
    const int*   src = (const int*)d_in[1];
    const int*   dst = (const int*)d_in[2];
    const float* W1  = (const float*)d_in[3];
    const float* b1  = (const float*)d_in[4];
    const float* W2  = (const float*)d_in[5];
    const float* b2  = (const float*)d_in[6];
    float* out = (float*)d_out;

    const int T = 256;
    int nodeBlocks = (N_NODES + T - 1) / T;
    int quadBlocks = (N_EDGES / 4 + T - 1) / T;
    int vec4Blocks = (N_NODES * D / 4 + T - 1) / T;
    int aggBlocks  = (int)(((long long)N_NODES * 32 + T - 1) / T);
    int gemmBlocks = (N_NODES + 127) / 128;

    // preprocessing: convert x/W1/W2 + zero counters, CSR build
    convert_zero_kernel<<<vec4Blocks, T>>>(x, W1, W2);
    deg_kernel<<<quadBlocks, T>>>(dst);
    alloc_rinv_kernel<<<nodeBlocks, T>>>();
    fill_kernel<<<quadBlocks, T>>>(src, dst);

    // layer 1
    agg_kernel<false><<<aggBlocks, T>>>();
    gemm_hmma_kernel<true><<<gemmBlocks, T>>>(b1, nullptr);

    // layer 2
    agg_kernel<true><<<aggBlocks, T>>>();
    gemm_hmma_kernel<false><<<gemmBlocks, T>>>(b2, out);
}